// round 8
// baseline (speedup 1.0000x reference)
#include <cuda_runtime.h>
#include <math.h>
#include <stdint.h>

#define BB 2048
#define SS 200
#define DD 192
#define H1 64
#define H2 32
#define NT 256
#define KT 24
#define NTILE 8
#define APAD 204     // A-tile k-row stride (floats)
#define SPAD 200     // Ht row stride

typedef unsigned long long ull;

// ---- smem layout (floats) ----
#define SM_WEFF 0                      // 12288 (dead after GEMM; Ht overlay)
#define SM_ABUF 12288                  // 2*KT*APAD = 9792
#define SM_QS   (SM_ABUF + 9792)       // 192
#define SM_B1   (SM_QS + 192)          // 64
#define SM_W2   (SM_B1 + 64)           // 2048 [h][k]
#define SM_W3   (SM_W2 + 2048)         // 32
#define SM_B2   (SM_W3 + 32)           // 32
#define SM_SC   (SM_B2 + 32)           // 256
#define SM_WGT  (SM_SC + 256)          // 256
#define SM_RED  (SM_WGT + 256)         // 64
#define SMEM_FLOATS (SM_RED + 64)      // 25024 floats = 100096 B (x2 per SM)

__device__ __forceinline__ ull pk2(float x) {
    ull r; asm("mov.b64 %0, {%1, %1};" : "=l"(r) : "f"(x)); return r;
}
__device__ __forceinline__ ull pk2p(float x, float y) {
    ull r; asm("mov.b64 %0, {%1, %2};" : "=l"(r) : "f"(x), "f"(y)); return r;
}
__device__ __forceinline__ void fma2(ull& d, ull a, ull b) {
    asm("fma.rn.f32x2 %0, %1, %2, %0;" : "+l"(d) : "l"(a), "l"(b));
}
__device__ __forceinline__ float2 up2(ull v) {
    float2 r; asm("mov.b64 {%0, %1}, %2;" : "=f"(r.x), "=f"(r.y) : "l"(v)); return r;
}

__global__ __launch_bounds__(NT, 2)
void rich_attn_kernel(const float* __restrict__ query,
                      const float* __restrict__ keys,
                      const int*   __restrict__ kmask,
                      const float* __restrict__ W1,
                      const float* __restrict__ b1,
                      const float* __restrict__ a1p,
                      const float* __restrict__ W2,
                      const float* __restrict__ b2,
                      const float* __restrict__ a2p,
                      const float* __restrict__ W3,
                      const float* __restrict__ b3p,
                      float* __restrict__ out)
{
    extern __shared__ float sm[];
    const int tid = threadIdx.x;
    const int b   = blockIdx.x;

    const float a1 = a1p[0];
    const float a2 = a2p[0];
    const float b3 = b3p[0];

    const float* kbase = keys + (size_t)b * SS * DD;

    float* weff  = sm + SM_WEFF;
    float* qs    = sm + SM_QS;
    float* bias1 = sm + SM_B1;
    float* w2s   = sm + SM_W2;
    float* w3s   = sm + SM_W3;
    float* b2s   = sm + SM_B2;
    float* score = sm + SM_SC;
    float* wgt   = sm + SM_WGT;
    float* red   = sm + SM_RED;

    // ---- loader mapping: per tile 200*KT floats = 1200 float4 ----
    float4 st[5];
    int   sf[5], kf[5];
    #pragma unroll
    for (int j = 0; j < 5; j++) {
        int f = tid + NT * j;
        if (f < 1200) { sf[j] = f / 6; kf[j] = f - 6 * sf[j]; }
        else          { sf[j] = -1; kf[j] = 0; }
    }

    // ---- prologue: LDG tile0, STS tile0 -> buf0, LDG tile1 -> regs ----
    #pragma unroll
    for (int j = 0; j < 5; j++)
        if (sf[j] >= 0)
            st[j] = *reinterpret_cast<const float4*>(kbase + (size_t)sf[j] * DD + 4 * kf[j]);
    {
        float* A0 = sm + SM_ABUF;
        #pragma unroll
        for (int j = 0; j < 5; j++)
            if (sf[j] >= 0) {
                int kk = 4 * kf[j], s = sf[j];
                A0[(kk+0)*APAD + s] = st[j].x; A0[(kk+1)*APAD + s] = st[j].y;
                A0[(kk+2)*APAD + s] = st[j].z; A0[(kk+3)*APAD + s] = st[j].w;
            }
    }
    #pragma unroll
    for (int j = 0; j < 5; j++)
        if (sf[j] >= 0)
            st[j] = *reinterpret_cast<const float4*>(kbase + KT + (size_t)sf[j] * DD + 4 * kf[j]);

    // ---- q + small weights ----
    if (tid < DD) qs[tid] = query[(size_t)b * DD + tid];
    for (int idx = tid; idx < H1 * H2; idx += NT) w2s[idx] = W2[idx];
    if (tid < H2) { w3s[tid] = W3[tid]; b2s[tid] = b2[tid]; }
    if (tid >= 200) score[tid] = -INFINITY;
    __syncthreads();   // qs ready, tile0 in smem

    // ---- weff[i][h] ----
    for (int idx = tid; idx < DD * 16; idx += NT) {
        int i  = idx >> 4;
        int h4 = (idx & 15) << 2;
        float  qv = qs[i];
        float4 r0 = *reinterpret_cast<const float4*>(W1 + (size_t)i * H1 + h4);
        float4 r1 = *reinterpret_cast<const float4*>(W1 + (size_t)(384 + i) * H1 + h4);
        float4 r2 = *reinterpret_cast<const float4*>(W1 + (size_t)(576 + i) * H1 + h4);
        float4 v;
        v.x = r0.x + r2.x + qv * r1.x;
        v.y = r0.y + r2.y + qv * r1.y;
        v.z = r0.z + r2.z + qv * r1.z;
        v.w = r0.w + r2.w + qv * r1.w;
        *reinterpret_cast<float4*>(weff + (size_t)i * H1 + h4) = v;
    }
    // ---- bias1 partials (use score[] scratch? no — use wgt region later; use red? red only 64; use w2s? no)
    // reuse SM_SC..: score[0..255] used later; use a reduction into red via shuffles instead:
    {
        int h = tid & 63;
        int c = tid >> 6;                 // 0..3, chunks of 48
        float acc_ = 0.f;
        int i0 = c * 48;
        #pragma unroll 4
        for (int i = i0; i < i0 + 48; i++)
            acc_ = fmaf(qs[i], W1[(size_t)(192 + i) * H1 + h] - W1[(size_t)(576 + i) * H1 + h], acc_);
        wgt[tid] = acc_;   // wgt as scratch (re-written later)
    }
    __syncthreads();
    if (tid < H1)
        bias1[tid] = b1[tid] + wgt[tid] + wgt[tid + 64] + wgt[tid + 128] + wgt[tid + 192];
    __syncthreads();

    // ---- GEMM: 200 comp threads, tile 8s x 8h, single barrier per tile ----
    const bool comp = (tid < 200);
    const int sg = tid >> 3;           // 0..24
    const int hg = tid & 7;            // 0..7
    const int s0 = sg * 8;
    const int h0 = hg * 8;

    ull acc[4][8];
    if (comp) {
        #pragma unroll
        for (int h = 0; h < 8; h++) {
            ull bi = pk2(bias1[h0 + h]);
            #pragma unroll
            for (int p = 0; p < 4; p++) acc[p][h] = bi;
        }
    }

    for (int t = 0; t < NTILE; t++) {
        // overlap: store tile t+1 (from regs) and fetch tile t+2 while computing t
        if (t + 1 < NTILE) {
            float* A0 = sm + SM_ABUF + ((t + 1) & 1) * KT * APAD;
            #pragma unroll
            for (int j = 0; j < 5; j++)
                if (sf[j] >= 0) {
                    int kk = 4 * kf[j], s = sf[j];
                    A0[(kk+0)*APAD + s] = st[j].x; A0[(kk+1)*APAD + s] = st[j].y;
                    A0[(kk+2)*APAD + s] = st[j].z; A0[(kk+3)*APAD + s] = st[j].w;
                }
            if (t + 2 < NTILE) {
                const float* g = kbase + (t + 2) * KT;
                #pragma unroll
                for (int j = 0; j < 5; j++)
                    if (sf[j] >= 0)
                        st[j] = *reinterpret_cast<const float4*>(g + (size_t)sf[j] * DD + 4 * kf[j]);
            }
        }
        if (comp) {
            const float* At = sm + SM_ABUF + (t & 1) * KT * APAD + s0;
            const float* Bt = weff + t * KT * H1 + h0;
            #pragma unroll 6
            for (int kk = 0; kk < KT; kk++) {
                ulonglong2 a01 = *reinterpret_cast<const ulonglong2*>(At + kk * APAD);
                ulonglong2 a23 = *reinterpret_cast<const ulonglong2*>(At + kk * APAD + 4);
                float4 bv0 = *reinterpret_cast<const float4*>(Bt + kk * H1);
                float4 bv1 = *reinterpret_cast<const float4*>(Bt + kk * H1 + 4);
                ull ap[4] = {a01.x, a01.y, a23.x, a23.y};
                ull bd[8] = {pk2(bv0.x), pk2(bv0.y), pk2(bv0.z), pk2(bv0.w),
                             pk2(bv1.x), pk2(bv1.y), pk2(bv1.z), pk2(bv1.w)};
                #pragma unroll
                for (int p = 0; p < 4; p++)
                    #pragma unroll
                    for (int h = 0; h < 8; h++)
                        fma2(acc[p][h], ap[p], bd[h]);
            }
        }
        __syncthreads();   // STS(t+1) visible; buf[t&1] free for STS(t+2)
    }

    // ---- prelu1 -> Ht[h][s] overlaying weff/Abuf ----
    float* Ht = sm;   // [64][SPAD]
    if (comp) {
        #pragma unroll
        for (int p = 0; p < 4; p++) {
            #pragma unroll
            for (int h = 0; h < 8; h++) {
                float2 v = up2(acc[p][h]);
                float v0 = (v.x >= 0.f) ? v.x : a1 * v.x;
                float v1 = (v.y >= 0.f) ? v.y : a1 * v.y;
                *reinterpret_cast<ull*>(Ht + (h0 + h) * SPAD + s0 + 2 * p) = pk2p(v0, v1);
            }
        }
    }
    __syncthreads();

    // ---- layers 2+3 per s ----
    if (tid < SS) {
        const int s = tid;
        ull acc2[16];
        {
            const ulonglong2* bp = reinterpret_cast<const ulonglong2*>(b2s);
            #pragma unroll
            for (int j = 0; j < 8; j++) { acc2[2*j] = bp[j].x; acc2[2*j+1] = bp[j].y; }
        }
        #pragma unroll 8
        for (int h = 0; h < H1; h++) {
            ull xx = pk2(Ht[h * SPAD + s]);
            const ulonglong2* wr = reinterpret_cast<const ulonglong2*>(w2s + h * H2);
            #pragma unroll
            for (int j4 = 0; j4 < 8; j4++) {
                ulonglong2 wv = wr[j4];
                fma2(acc2[2*j4],   xx, wv.x);
                fma2(acc2[2*j4+1], xx, wv.y);
            }
        }
        float sc = b3;
        #pragma unroll
        for (int j = 0; j < 16; j++) {
            float2 p = up2(acc2[j]);
            float v0 = (p.x >= 0.f) ? p.x : a2 * p.x;
            float v1 = (p.y >= 0.f) ? p.y : a2 * p.y;
            sc = fmaf(v0, w3s[2*j], sc);
            sc = fmaf(v1, w3s[2*j + 1], sc);
        }
        int mv = kmask[(size_t)b * SS + s];
        score[s] = mv ? sc : -INFINITY;
    }
    __syncthreads();

    // ---- softmax via warp shuffles (4 barriers total) ----
    const float myscore = score[tid];          // -INF padded for tid>=200
    float v = myscore;
    #pragma unroll
    for (int off = 16; off > 0; off >>= 1)
        v = fmaxf(v, __shfl_xor_sync(0xffffffffu, v, off));
    if ((tid & 31) == 0) red[tid >> 5] = v;
    __syncthreads();
    if (tid < 32) {
        float mv = (tid < 8) ? red[tid] : -INFINITY;
        #pragma unroll
        for (int off = 4; off > 0; off >>= 1)
            mv = fmaxf(mv, __shfl_xor_sync(0xffffffffu, mv, off));
        if (tid == 0) red[32] = mv;
    }
    __syncthreads();
    const float m = red[32];

    float e = 0.f;
    if (tid < SS && m > -INFINITY && myscore > -INFINITY)
        e = expf(myscore - m);
    float es = e;
    #pragma unroll
    for (int off = 16; off > 0; off >>= 1)
        es += __shfl_xor_sync(0xffffffffu, es, off);
    if ((tid & 31) == 0) red[tid >> 5] = es;
    __syncthreads();
    if (tid < 32) {
        float sv = (tid < 8) ? red[tid] : 0.f;
        #pragma unroll
        for (int off = 4; off > 0; off >>= 1)
            sv += __shfl_xor_sync(0xffffffffu, sv, off);
        if (tid == 0) red[32] = (sv > 0.f) ? (1.f / sv) : 0.f;
    }
    __syncthreads();
    const float inv = red[32];

    {
        float wv = e * inv;
        wgt[tid] = wv;
        if (tid < SS) out[(size_t)BB * DD + (size_t)b * SS + tid] = wv;
    }
    __syncthreads();

    // ---- weighted sum: out[b,d] = sum_s wgt[s]*keys[b,s,d] ----
    if (tid < DD) {
        const float* kb = kbase + tid;
        float accw = 0.f;
        #pragma unroll 8
        for (int si = 0; si < SS; si++)
            accw = fmaf(wgt[si], kb[(size_t)si * DD], accw);
        out[(size_t)b * DD + tid] = accw;
    }
}

extern "C" void kernel_launch(void* const* d_in, const int* in_sizes, int n_in,
                              void* d_out, int out_size)
{
    const float* query = (const float*)d_in[0];
    const float* keys  = (const float*)d_in[1];
    const int*   mask  = (const int*)  d_in[2];
    const float* W1    = (const float*)d_in[3];
    const float* b1    = (const float*)d_in[4];
    const float* a1    = (const float*)d_in[5];
    const float* W2    = (const float*)d_in[6];
    const float* b2    = (const float*)d_in[7];
    const float* a2    = (const float*)d_in[8];
    const float* W3    = (const float*)d_in[9];
    const float* b3    = (const float*)d_in[10];
    float* out = (float*)d_out;

    static bool attr_set = false;
    if (!attr_set) {
        cudaFuncSetAttribute(rich_attn_kernel,
                             cudaFuncAttributeMaxDynamicSharedMemorySize,
                             SMEM_FLOATS * sizeof(float));
        attr_set = true;
    }

    rich_attn_kernel<<<BB, NT, SMEM_FLOATS * sizeof(float)>>>(
        query, keys, mask, W1, b1, a1, W2, b2, a2, W3, b3, out);
}